// round 1
// baseline (speedup 1.0000x reference)
#include <cuda_runtime.h>
#include <math.h>

#define BB   16
#define NN   16000
#define GG   128
#define NPG  (NN + GG)
#define IMGW 800.0f
#define IMGH 800.0f
#define XCLIP 4.135166556742356f   /* log(1000/16) */

__device__ __forceinline__ float4 ld4(const float* p) {
    return *reinterpret_cast<const float4*>(p);
}

// ---------------------------------------------------------------------------
// Kernel 1: labels. One thread per (b, proposal p in [0, N+G)).
// Loops over 128 GT boxes in shared memory (warp-broadcast reads).
// Division only on positive intersection (~1% of pairs).
// ---------------------------------------------------------------------------
__global__ void labels_kernel(const float* __restrict__ props,
                              const float* __restrict__ gts,
                              float* __restrict__ out_labels) {
    __shared__ float4 sg[GG];
    __shared__ float  sa[GG];
    const int b   = blockIdx.y;
    const int tid = threadIdx.x;
    const float* gt_b = gts + (size_t)b * GG * 4;

    for (int g = tid; g < GG; g += blockDim.x) {
        float4 v = ld4(gt_b + g * 4);
        sg[g] = v;
        sa[g] = __fmul_rn(__fsub_rn(v.z, v.x), __fsub_rn(v.w, v.y));
    }
    __syncthreads();

    const int p = blockIdx.x * blockDim.x + tid;
    if (p >= NPG) return;

    float4 a = (p < NN) ? ld4(props + ((size_t)b * NN + p) * 4)
                        : ld4(gt_b + (size_t)(p - NN) * 4);
    const float area_a = __fmul_rn(__fsub_rn(a.z, a.x), __fsub_rn(a.w, a.y));

    float vmax = 0.0f;
#pragma unroll 4
    for (int g = 0; g < GG; g++) {
        float4 bb = sg[g];
        float ltx = fmaxf(a.x, bb.x);
        float lty = fmaxf(a.y, bb.y);
        float rbx = fminf(a.z, bb.z);
        float rby = fminf(a.w, bb.w);
        float w = __fsub_rn(rbx, ltx);
        float h = __fsub_rn(rby, lty);
        if (w > 0.0f && h > 0.0f) {
            float inter = __fmul_rn(w, h);
            float uni   = __fsub_rn(__fadd_rn(sa[g], area_a), inter);
            float q     = __fdiv_rn(inter, uni);
            vmax = fmaxf(vmax, q);
        }
    }
    out_labels[(size_t)b * NPG + p] = (vmax >= 0.5f) ? 1.0f : 0.0f;
}

// ---------------------------------------------------------------------------
// Kernel 2: per-GT argmax over first N proposals + encode + roi_scores.
// 8 GTs per block so each proposal float4 is loaded once per 8 IoUs
// (cuts L2 traffic 8x vs 1 GT/block). Exact rounded-quotient argmax with
// first-index tie semantics (lexicographic max on (q, -idx) — commutative).
// ---------------------------------------------------------------------------
#define GPB 8
__global__ void match_kernel(const float* __restrict__ props,
                             const float* __restrict__ gts,
                             float* __restrict__ out_regt,
                             float* __restrict__ out_scores) {
    __shared__ float4 sgt[GPB];
    __shared__ float  sga[GPB];
    __shared__ float  sq[GPB * 256];
    __shared__ int    si[GPB * 256];

    const int b   = blockIdx.y;
    const int g0  = blockIdx.x * GPB;
    const int tid = threadIdx.x;
    const float* gt_b = gts + ((size_t)b * GG) * 4;
    const float* pb   = props + (size_t)b * NN * 4;

    if (tid < GPB) {
        float4 v = ld4(gt_b + (size_t)(g0 + tid) * 4);
        sgt[tid] = v;
        sga[tid] = __fmul_rn(__fsub_rn(v.z, v.x), __fsub_rn(v.w, v.y));
    }
    __syncthreads();

    float bq[GPB];
    int   bi[GPB];
#pragma unroll
    for (int r = 0; r < GPB; r++) { bq[r] = 0.0f; bi[r] = tid; }

    for (int p = tid; p < NN; p += 256) {
        float4 a = ld4(pb + (size_t)p * 4);
        float area_p = __fmul_rn(__fsub_rn(a.z, a.x), __fsub_rn(a.w, a.y));
#pragma unroll
        for (int r = 0; r < GPB; r++) {
            float4 gb = sgt[r];
            float ltx = fmaxf(gb.x, a.x);
            float lty = fmaxf(gb.y, a.y);
            float rbx = fminf(gb.z, a.z);
            float rby = fminf(gb.w, a.w);
            float w = __fsub_rn(rbx, ltx);
            float h = __fsub_rn(rby, lty);
            if (w > 0.0f && h > 0.0f) {
                float inter = __fmul_rn(w, h);
                float uni   = __fsub_rn(__fadd_rn(sga[r], area_p), inter);
                float q     = __fdiv_rn(inter, uni);
                if (q > bq[r]) { bq[r] = q; bi[r] = p; }
            }
        }
    }

#pragma unroll
    for (int r = 0; r < GPB; r++) { sq[r * 256 + tid] = bq[r]; si[r * 256 + tid] = bi[r]; }
    __syncthreads();

    // warp w reduces row w (256 entries): 8 serial per lane + shuffle tree
    const int w    = tid >> 5;
    const int lane = tid & 31;
    float rq = sq[w * 256 + lane];
    int   ri = si[w * 256 + lane];
#pragma unroll
    for (int k = 1; k < 8; k++) {
        float q2 = sq[w * 256 + lane + 32 * k];
        int   i2 = si[w * 256 + lane + 32 * k];
        if (q2 > rq || (q2 == rq && i2 < ri)) { rq = q2; ri = i2; }
    }
#pragma unroll
    for (int s = 16; s > 0; s >>= 1) {
        float q2 = __shfl_down_sync(0xFFFFFFFFu, rq, s);
        int   i2 = __shfl_down_sync(0xFFFFFFFFu, ri, s);
        if (q2 > rq || (q2 == rq && i2 < ri)) { rq = q2; ri = i2; }
    }

    if (lane == 0) {
        const int g = g0 + w;
        float4 mp = ld4(pb + (size_t)ri * 4);
        float4 gb = sgt[w];
        float pw  = __fsub_rn(mp.z, mp.x);
        float ph  = __fsub_rn(mp.w, mp.y);
        float pcx = __fadd_rn(mp.x, __fmul_rn(0.5f, pw));
        float pcy = __fadd_rn(mp.y, __fmul_rn(0.5f, ph));
        float gw  = __fsub_rn(gb.z, gb.x);
        float gh  = __fsub_rn(gb.w, gb.y);
        float gcx = __fadd_rn(gb.x, __fmul_rn(0.5f, gw));
        float gcy = __fadd_rn(gb.y, __fmul_rn(0.5f, gh));
        float dx = __fdiv_rn(__fmul_rn(10.0f, __fsub_rn(gcx, pcx)), pw);
        float dy = __fdiv_rn(__fmul_rn(10.0f, __fsub_rn(gcy, pcy)), ph);
        float dw = __fmul_rn(5.0f, logf(__fdiv_rn(gw, pw)));
        float dh = __fmul_rn(5.0f, logf(__fdiv_rn(gh, ph)));
        float* o = out_regt + ((size_t)b * GG + g) * 4;
        o[0] = dx; o[1] = dy; o[2] = dw; o[3] = dh;
        out_scores[(size_t)b * GG + g] = rq;
    }
}

// ---------------------------------------------------------------------------
// Kernel 3: decode + clip over all B*(N+G) boxes.
// ---------------------------------------------------------------------------
__global__ void decode_kernel(const float* __restrict__ props,
                              const float* __restrict__ gts,
                              const float* __restrict__ reg,
                              float* __restrict__ out_pred) {
    const int i = blockIdx.x * blockDim.x + threadIdx.x;
    if (i >= BB * NPG) return;
    const int b = i / NPG;
    const int p = i - b * NPG;

    float4 pr = (p < NN) ? ld4(props + ((size_t)b * NN + p) * 4)
                         : ld4(gts + ((size_t)b * GG + (p - NN)) * 4);
    float4 r = ld4(reg + (size_t)i * 4);

    float pw  = __fsub_rn(pr.z, pr.x);
    float ph  = __fsub_rn(pr.w, pr.y);
    float pcx = __fadd_rn(pr.x, __fmul_rn(0.5f, pw));
    float pcy = __fadd_rn(pr.y, __fmul_rn(0.5f, ph));

    float dx = __fdiv_rn(r.x, 10.0f);
    float dy = __fdiv_rn(r.y, 10.0f);
    float dw = fminf(__fdiv_rn(r.z, 5.0f), XCLIP);
    float dh = fminf(__fdiv_rn(r.w, 5.0f), XCLIP);

    float ncx = __fadd_rn(__fmul_rn(dx, pw), pcx);
    float ncy = __fadd_rn(__fmul_rn(dy, ph), pcy);
    float nw  = __fmul_rn(expf(dw), pw);
    float nh  = __fmul_rn(expf(dh), ph);

    float x0 = __fsub_rn(ncx, __fmul_rn(0.5f, nw));
    float y0 = __fsub_rn(ncy, __fmul_rn(0.5f, nh));
    float x1 = __fadd_rn(ncx, __fmul_rn(0.5f, nw));
    float y1 = __fadd_rn(ncy, __fmul_rn(0.5f, nh));

    float4 o;
    o.x = fminf(fmaxf(x0, 0.0f), IMGW);
    o.y = fminf(fmaxf(y0, 0.0f), IMGH);
    o.z = fminf(fmaxf(x1, 0.0f), IMGW);
    o.w = fminf(fmaxf(y1, 0.0f), IMGH);
    *reinterpret_cast<float4*>(out_pred + (size_t)i * 4) = o;
}

// ---------------------------------------------------------------------------
extern "C" void kernel_launch(void* const* d_in, const int* in_sizes, int n_in,
                              void* d_out, int out_size) {
    const float* props = (const float*)d_in[0];   // (B, N, 4)
    const float* gts   = (const float*)d_in[1];   // (B, G, 4)
    const float* reg   = (const float*)d_in[2];   // (B, N+G, 4)

    float* out        = (float*)d_out;
    float* out_pred   = out;                                  // B*(N+G)*4
    float* out_regt   = out_pred + (size_t)BB * NPG * 4;      // B*G*4
    float* out_scores = out_regt + (size_t)BB * GG * 4;       // B*G
    float* out_labels = out_scores + (size_t)BB * GG;         // B*(N+G)

    dim3 gl((NPG + 255) / 256, BB);
    labels_kernel<<<gl, 256>>>(props, gts, out_labels);

    dim3 gm(GG / GPB, BB);
    match_kernel<<<gm, 256>>>(props, gts, out_regt, out_scores);

    int tot = BB * NPG;
    decode_kernel<<<(tot + 255) / 256, 256>>>(props, gts, reg, out_pred);
}

// round 2
// speedup vs baseline: 2.2547x; 2.2547x over previous
#include <cuda_runtime.h>
#include <math.h>

#define BB   16
#define NN   16000
#define GG   128
#define NPG  (NN + GG)
#define IMGW 800.0f
#define IMGH 800.0f
#define XCLIP 4.135166556742356f   /* log(1000/16) */

#define NBX   7          /* 7x7 bins of 128px cover 800x800 */
#define NBINS (NBX * NBX)
#define BINW_INV (1.0f / 128.0f)
#define CAP   128        /* exact upper bound: at most G entries per bin */

// Cross-block scratch for per-GT argmax keys: (q_bits << 32) | (~idx)
__device__ unsigned long long g_keys[BB * GG];

__device__ __forceinline__ float4 ld4(const float* p) {
    return *reinterpret_cast<const float4*>(p);
}

// ---------------------------------------------------------------------------
// Kernel 0: reset argmax keys to (q=0, idx=0)  -> key = 0x00000000FFFFFFFF
// ---------------------------------------------------------------------------
__global__ void init_keys_kernel() {
    int i = blockIdx.x * blockDim.x + threadIdx.x;
    if (i < BB * GG) g_keys[i] = 0xFFFFFFFFull;
}

// ---------------------------------------------------------------------------
// Kernel 1 (fused): per-proposal decode+clip, labels (max IoU vs 0.5), and
// per-GT argmax via atomicMax on hits only. GTs spatially binned in smem;
// each proposal only tests GTs sharing one of its <=4 bins.
// ---------------------------------------------------------------------------
__global__ __launch_bounds__(256)
void main_kernel(const float* __restrict__ props,
                 const float* __restrict__ gts,
                 const float* __restrict__ reg,
                 float* __restrict__ out_pred,
                 float* __restrict__ out_labels) {
    __shared__ float4        sg[GG];
    __shared__ float         sa[GG];
    __shared__ int           scnt[NBINS];
    __shared__ unsigned char sent[NBINS * CAP];

    const int b   = blockIdx.y;
    const int tid = threadIdx.x;
    const float* gt_b = gts + (size_t)b * GG * 4;

    if (tid < NBINS) scnt[tid] = 0;
    __syncthreads();

    if (tid < GG) {
        float4 v = ld4(gt_b + tid * 4);
        sg[tid] = v;
        sa[tid] = __fmul_rn(__fsub_rn(v.z, v.x), __fsub_rn(v.w, v.y));
        int bx0 = (int)(v.x * BINW_INV);
        int bx1 = (int)(v.z * BINW_INV); if (bx1 > NBX - 1) bx1 = NBX - 1;
        int by0 = (int)(v.y * BINW_INV);
        int by1 = (int)(v.w * BINW_INV); if (by1 > NBX - 1) by1 = NBX - 1;
        for (int by = by0; by <= by1; by++)
            for (int bx = bx0; bx <= bx1; bx++) {
                int bin = by * NBX + bx;
                int pos = atomicAdd(&scnt[bin], 1);
                sent[bin * CAP + pos] = (unsigned char)tid;
            }
    }
    __syncthreads();

    const int p = blockIdx.x * 256 + tid;
    if (p >= NPG) return;

    float4 a = (p < NN) ? ld4(props + ((size_t)b * NN + p) * 4) : sg[p - NN];

    // ---- decode + clip (pred_boxes) ----
    {
        float4 r = ld4(reg + ((size_t)b * NPG + p) * 4);
        float pw  = __fsub_rn(a.z, a.x);
        float ph  = __fsub_rn(a.w, a.y);
        float pcx = __fadd_rn(a.x, __fmul_rn(0.5f, pw));
        float pcy = __fadd_rn(a.y, __fmul_rn(0.5f, ph));
        float dx = __fdiv_rn(r.x, 10.0f);
        float dy = __fdiv_rn(r.y, 10.0f);
        float dw = fminf(__fdiv_rn(r.z, 5.0f), XCLIP);
        float dh = fminf(__fdiv_rn(r.w, 5.0f), XCLIP);
        float ncx = __fadd_rn(__fmul_rn(dx, pw), pcx);
        float ncy = __fadd_rn(__fmul_rn(dy, ph), pcy);
        float nw  = __fmul_rn(expf(dw), pw);
        float nh  = __fmul_rn(expf(dh), ph);
        float4 o;
        o.x = fminf(fmaxf(__fsub_rn(ncx, __fmul_rn(0.5f, nw)), 0.0f), IMGW);
        o.y = fminf(fmaxf(__fsub_rn(ncy, __fmul_rn(0.5f, nh)), 0.0f), IMGH);
        o.z = fminf(fmaxf(__fadd_rn(ncx, __fmul_rn(0.5f, nw)), 0.0f), IMGW);
        o.w = fminf(fmaxf(__fadd_rn(ncy, __fmul_rn(0.5f, nh)), 0.0f), IMGH);
        *reinterpret_cast<float4*>(out_pred + ((size_t)b * NPG + p) * 4) = o;
    }

    // ---- IoU pass over binned GT candidates ----
    const float area_a = __fmul_rn(__fsub_rn(a.z, a.x), __fsub_rn(a.w, a.y));
    float vmax = 0.0f;
    unsigned long long* keyrow = g_keys + b * GG;
    const unsigned low = 0xFFFFFFFFu - (unsigned)p;
    const bool isprop = (p < NN);

    int bx0 = (int)(a.x * BINW_INV);
    int bx1 = (int)(a.z * BINW_INV); if (bx1 > NBX - 1) bx1 = NBX - 1;
    int by0 = (int)(a.y * BINW_INV);
    int by1 = (int)(a.w * BINW_INV); if (by1 > NBX - 1) by1 = NBX - 1;

    for (int by = by0; by <= by1; by++)
        for (int bx = bx0; bx <= bx1; bx++) {
            int bin = by * NBX + bx;
            int cnt = scnt[bin];
            const unsigned char* ent = sent + bin * CAP;
            for (int k = 0; k < cnt; k++) {
                int g = ent[k];
                float4 gb = sg[g];
                float ltx = fmaxf(a.x, gb.x);
                float lty = fmaxf(a.y, gb.y);
                float rbx = fminf(a.z, gb.z);
                float rby = fminf(a.w, gb.w);
                float w = __fsub_rn(rbx, ltx);
                float h = __fsub_rn(rby, lty);
                if (w > 0.0f && h > 0.0f) {
                    float inter = __fmul_rn(w, h);
                    float uni   = __fsub_rn(__fadd_rn(sa[g], area_a), inter);
                    float q     = __fdiv_rn(inter, uni);
                    vmax = fmaxf(vmax, q);
                    if (isprop) {
                        unsigned long long key =
                            ((unsigned long long)__float_as_uint(q) << 32) | low;
                        atomicMax(keyrow + g, key);
                    }
                }
            }
        }

    out_labels[(size_t)b * NPG + p] = (vmax >= 0.5f) ? 1.0f : 0.0f;
}

// ---------------------------------------------------------------------------
// Kernel 2: decode argmax keys -> encode reg targets + roi_scores (B*G threads)
// ---------------------------------------------------------------------------
__global__ void epilogue_kernel(const float* __restrict__ props,
                                const float* __restrict__ gts,
                                float* __restrict__ out_regt,
                                float* __restrict__ out_scores) {
    int i = blockIdx.x * blockDim.x + threadIdx.x;
    if (i >= BB * GG) return;
    int b = i / GG;
    int g = i - b * GG;

    unsigned long long key = g_keys[i];
    unsigned idx = 0xFFFFFFFFu - (unsigned)(key & 0xFFFFFFFFull);
    float q = __uint_as_float((unsigned)(key >> 32));

    float4 mp = ld4(props + ((size_t)b * NN + idx) * 4);
    float4 gb = ld4(gts + ((size_t)b * GG + g) * 4);

    float pw  = __fsub_rn(mp.z, mp.x);
    float ph  = __fsub_rn(mp.w, mp.y);
    float pcx = __fadd_rn(mp.x, __fmul_rn(0.5f, pw));
    float pcy = __fadd_rn(mp.y, __fmul_rn(0.5f, ph));
    float gw  = __fsub_rn(gb.z, gb.x);
    float gh  = __fsub_rn(gb.w, gb.y);
    float gcx = __fadd_rn(gb.x, __fmul_rn(0.5f, gw));
    float gcy = __fadd_rn(gb.y, __fmul_rn(0.5f, gh));

    float dx = __fdiv_rn(__fmul_rn(10.0f, __fsub_rn(gcx, pcx)), pw);
    float dy = __fdiv_rn(__fmul_rn(10.0f, __fsub_rn(gcy, pcy)), ph);
    float dw = __fmul_rn(5.0f, logf(__fdiv_rn(gw, pw)));
    float dh = __fmul_rn(5.0f, logf(__fdiv_rn(gh, ph)));

    float* o = out_regt + (size_t)i * 4;
    o[0] = dx; o[1] = dy; o[2] = dw; o[3] = dh;
    out_scores[i] = q;
}

// ---------------------------------------------------------------------------
extern "C" void kernel_launch(void* const* d_in, const int* in_sizes, int n_in,
                              void* d_out, int out_size) {
    const float* props = (const float*)d_in[0];   // (B, N, 4)
    const float* gts   = (const float*)d_in[1];   // (B, G, 4)
    const float* reg   = (const float*)d_in[2];   // (B, N+G, 4)

    float* out        = (float*)d_out;
    float* out_pred   = out;                                  // B*(N+G)*4
    float* out_regt   = out_pred + (size_t)BB * NPG * 4;      // B*G*4
    float* out_scores = out_regt + (size_t)BB * GG * 4;       // B*G
    float* out_labels = out_scores + (size_t)BB * GG;         // B*(N+G)

    init_keys_kernel<<<(BB * GG + 255) / 256, 256>>>();

    dim3 gm((NPG + 255) / 256, BB);
    main_kernel<<<gm, 256>>>(props, gts, reg, out_pred, out_labels);

    epilogue_kernel<<<(BB * GG + 255) / 256, 256>>>(props, gts, out_regt, out_scores);
}